// round 5
// baseline (speedup 1.0000x reference)
#include <cuda_runtime.h>
#include <cuda_bf16.h>
#include <cstdint>

// ============================================================
// Attention1D: LN -> QKV GEMM -> 8-head window attention -> out GEMM
// Generic-PTX path (mma.sync tf32 + cp.async); tcgen05 unavailable
// because the harness PTX stage targets compute_103 (no 'a').
// ============================================================

#define NCTA 2048

// weight scratch (tf32-rounded, transposed)
__device__ __align__(16) float g_w1t[8 * 96 * 256];   // [h][j=q|k|v 96][k 256]
__device__ __align__(16) float g_w2t[256 * 256];      // [n][k]
// attention-output scratch (tf32-rounded fp32), 268 MB
__device__ float g_a2[67108864];                      // [262144][256]

static __device__ __forceinline__ uint32_t smem_u32(const void* p) {
    uint32_t a;
    asm("{ .reg .u64 t; cvta.to.shared.u64 t, %1; cvt.u32.u64 %0, t; }" : "=r"(a) : "l"(p));
    return a;
}
static __device__ __forceinline__ float f2tf(float f) {
    uint32_t o; asm("cvt.rna.tf32.f32 %0, %1;" : "=r"(o) : "f"(f));
    return __uint_as_float(o);
}
static __device__ __forceinline__ void mma8(float* c, const uint32_t* a,
                                            uint32_t b0, uint32_t b1) {
    asm volatile(
        "mma.sync.aligned.m16n8k8.row.col.f32.tf32.tf32.f32 "
        "{%0,%1,%2,%3}, {%4,%5,%6,%7}, {%8,%9}, {%0,%1,%2,%3};"
        : "+f"(c[0]), "+f"(c[1]), "+f"(c[2]), "+f"(c[3])
        : "r"(a[0]), "r"(a[1]), "r"(a[2]), "r"(a[3]), "r"(b0), "r"(b1));
}
#define CP16(dst, src) \
    asm volatile("cp.async.ca.shared.global [%0], [%1], 16;" :: "r"(dst), "l"(src))
#define CP_COMMIT() asm volatile("cp.async.commit_group;" ::: "memory")
#define CP_WAIT(n)  asm volatile("cp.async.wait_group %0;" :: "n"(n) : "memory")

// ---------------- weight prep ----------------
__global__ void prep_w1(const float* __restrict__ wqkv) {
    int o = blockIdx.x * 256 + threadIdx.x;          // < 196608
    int h  = o / 24576;
    int r  = o % 24576;
    int j  = r >> 8;                                 // 0..95 (q 0-31, k 32-63, v 64-95)
    int kk = r & 255;
    int sel = j >> 5, jj = j & 31;
    g_w1t[o] = f2tf(wqkv[kk * 768 + sel * 256 + h * 32 + jj]);
}
__global__ void prep_w2(const float* __restrict__ wout) {
    int o = blockIdx.x * 256 + threadIdx.x;          // < 65536
    int n = o >> 8, k = o & 255;
    g_w2t[o] = f2tf(wout[k * 256 + n]);
}

// ============================================================
// K1: LN + QKV GEMM + attention -> g_a2
// smem: xn [128][256] swizzled (131072 B) + B1 2x[96][64] (49152 B)
// ============================================================
#define K1_SMEM 180224

__global__ void __launch_bounds__(256, 1) attn_k1(
    const float* __restrict__ x, const float* __restrict__ lnw,
    const float* __restrict__ lnb, const float* __restrict__ relt)
{
    extern __shared__ float sm[];
    float* const sxn = sm;              // 32768 floats
    float* const sb1 = sm + 32768;      // 2 * 6144 floats
    const int tid  = threadIdx.x;
    const int wid  = tid >> 5;
    const int lane = tid & 31;
    const int g = lane >> 2, t = lane & 3;
    const int sw = g << 2;
    const int cta = blockIdx.x;
    const uint32_t sb1_u = smem_u32(sb1);

    // ---- stage chunk (h = cid>>2, k-quarter = cid&3) via cp.async ----
    auto stage = [&](int cid2) {
        const int h2 = cid2 >> 2, q2 = cid2 & 3, bf = cid2 & 1;
        const float* src = g_w1t + h2 * 24576 + q2 * 64;
        const uint32_t dstb = sb1_u + bf * 24576;
        #pragma unroll
        for (int i = 0; i < 6; ++i) {
            int idx = tid + i * 256;                 // 0..1535
            int j = idx >> 4, c4 = (idx & 15) * 4;
            uint32_t dst = dstb + (uint32_t)(j * 64 + (c4 ^ ((j & 7) << 2))) * 4u;
            CP16(dst, src + j * 256 + c4);
        }
        CP_COMMIT();
    };
    stage(0);
    stage(1);

    // ---- LayerNorm -> swizzled tf32 xn ----
    {
        const float* xr = x + (size_t)cta * 128 * 256;
        const float4 w0 = *(const float4*)(lnw + lane * 4);
        const float4 w1 = *(const float4*)(lnw + 128 + lane * 4);
        const float4 b0 = *(const float4*)(lnb + lane * 4);
        const float4 b1 = *(const float4*)(lnb + 128 + lane * 4);
        #pragma unroll 4
        for (int rr = 0; rr < 16; ++rr) {
            const int r = wid * 16 + rr;
            const float4 xa = *(const float4*)(xr + r * 256 + lane * 4);
            const float4 xb = *(const float4*)(xr + r * 256 + 128 + lane * 4);
            float s  = xa.x + xa.y + xa.z + xa.w + xb.x + xb.y + xb.z + xb.w;
            float ss = xa.x*xa.x + xa.y*xa.y + xa.z*xa.z + xa.w*xa.w
                     + xb.x*xb.x + xb.y*xb.y + xb.z*xb.z + xb.w*xb.w;
            #pragma unroll
            for (int o2 = 16; o2; o2 >>= 1) {
                s  += __shfl_xor_sync(0xffffffffu, s,  o2);
                ss += __shfl_xor_sync(0xffffffffu, ss, o2);
            }
            const float mu   = s * (1.0f / 256.0f);
            const float rstd = rsqrtf(ss * (1.0f / 256.0f) - mu * mu + 1e-5f);
            float4 pa, pb;
            pa.x = f2tf((xa.x - mu) * rstd * w0.x + b0.x);
            pa.y = f2tf((xa.y - mu) * rstd * w0.y + b0.y);
            pa.z = f2tf((xa.z - mu) * rstd * w0.z + b0.z);
            pa.w = f2tf((xa.w - mu) * rstd * w0.w + b0.w);
            pb.x = f2tf((xb.x - mu) * rstd * w1.x + b1.x);
            pb.y = f2tf((xb.y - mu) * rstd * w1.y + b1.y);
            pb.z = f2tf((xb.z - mu) * rstd * w1.z + b1.z);
            pb.w = f2tf((xb.w - mu) * rstd * w1.w + b1.w);
            const int srw = (r & 7) << 2;
            *(float4*)(sxn + r * 256 + ((lane * 4) ^ srw))       = pa;
            *(float4*)(sxn + r * 256 + 128 + ((lane * 4) ^ srw)) = pb;
        }
    }

    float acc[12][4];
    #pragma unroll
    for (int n = 0; n < 12; ++n)
        #pragma unroll
        for (int e = 0; e < 4; ++e) acc[n][e] = 0.0f;

    const int w16 = wid * 16;
    const float* const xrow = sxn + (w16 + g) * 256;
    const float scale = 0.17677669529663689f;        // 32^-0.5

    // ---- main loop: 8 heads x 4 k-chunks, 2-stage cp.async pipeline ----
    #pragma unroll 1
    for (int cid = 0; cid < 32; ++cid) {
        const int h = cid >> 2, q = cid & 3, bf = cid & 1;
        if (cid == 31) { CP_WAIT(0); } else { CP_WAIT(1); }
        __syncthreads();

        const float* const bw = sb1 + bf * 6144 + g * 64;
        const int qo = q * 64;
        #pragma unroll
        for (int ks = 0; ks < 8; ++ks) {
            const int o1 = (ks * 8 + t) ^ sw;
            const int o2 = (ks * 8 + t + 4) ^ sw;
            uint32_t a[4];
            a[0] = __float_as_uint(xrow[qo + o1]);
            a[1] = __float_as_uint(xrow[qo + o1 + 2048]);
            a[2] = __float_as_uint(xrow[qo + o2]);
            a[3] = __float_as_uint(xrow[qo + o2 + 2048]);
            #pragma unroll
            for (int n = 0; n < 12; ++n) {
                const uint32_t b0 = __float_as_uint(bw[n * 512 + o1]);
                const uint32_t b1 = __float_as_uint(bw[n * 512 + o2]);
                mma8(acc[n], a, b0, b1);
            }
        }

        if (q == 3) {
            // ---- attention for head h (pure intra-warp shuffles) ----
            float bias[8];
            #pragma unroll
            for (int j = 0; j < 8; ++j) {
                int ridx = (g >= 1 && j >= 1) ? (g - j + 6) : 13;
                bias[j] = __ldg(relt + ridx * 8 + h);
            }
            #pragma unroll
            for (int bb = 0; bb < 2; ++bb) {         // bb=0: rows g, bb=1: rows g+8
                float qv[8], kv[8], vv[8];
                #pragma unroll
                for (int n = 0; n < 4; ++n) {
                    qv[2*n] = acc[n][2*bb];     qv[2*n+1] = acc[n][2*bb+1];
                    kv[2*n] = acc[4+n][2*bb];   kv[2*n+1] = acc[4+n][2*bb+1];
                    vv[2*n] = acc[8+n][2*bb];   vv[2*n+1] = acc[8+n][2*bb+1];
                }
                float simv[8];
                #pragma unroll
                for (int j = 0; j < 8; ++j) {
                    float p = 0.0f;
                    #pragma unroll
                    for (int r = 0; r < 8; ++r) {
                        float kj = __shfl_sync(0xffffffffu, kv[r], (j << 2) | t);
                        p = fmaf(qv[r], kj, p);
                    }
                    p += __shfl_xor_sync(0xffffffffu, p, 1);
                    p += __shfl_xor_sync(0xffffffffu, p, 2);
                    simv[j] = p * scale + bias[j];
                }
                float mx = simv[0];
                #pragma unroll
                for (int j = 1; j < 8; ++j) mx = fmaxf(mx, simv[j]);
                float ssum = 0.0f;
                #pragma unroll
                for (int j = 0; j < 8; ++j) { simv[j] = __expf(simv[j] - mx); ssum += simv[j]; }
                const float inv = 1.0f / ssum;
                float ov[8];
                #pragma unroll
                for (int r = 0; r < 8; ++r) ov[r] = 0.0f;
                #pragma unroll
                for (int j = 0; j < 8; ++j) {
                    const float aj = simv[j] * inv;
                    #pragma unroll
                    for (int r = 0; r < 8; ++r) {
                        float vj = __shfl_sync(0xffffffffu, vv[r], (j << 2) | t);
                        ov[r] = fmaf(aj, vj, ov[r]);
                    }
                }
                const size_t row = (size_t)cta * 128 + w16 + g + bb * 8;
                float* dst = g_a2 + row * 256 + h * 32 + 2 * t;
                #pragma unroll
                for (int n = 0; n < 4; ++n) {
                    float2 p2;
                    p2.x = f2tf(ov[2*n]);
                    p2.y = f2tf(ov[2*n+1]);
                    *(float2*)(dst + n * 8) = p2;
                }
            }
            #pragma unroll
            for (int n = 0; n < 12; ++n)
                #pragma unroll
                for (int e = 0; e < 4; ++e) acc[n][e] = 0.0f;
        }
        __syncthreads();
        if (cid + 2 < 32) stage(cid + 2);
    }
}

// ============================================================
// K2: out = g_a2 @ w_out   (128-row CTA, N=256, K=256 in 4 chunks)
// smem: A 2x[128][64] (65536 B) + B 2x[256][64] (131072 B)
// ============================================================
#define K2_SMEM 196608

__global__ void __launch_bounds__(256, 1) attn_k2(float* __restrict__ out)
{
    extern __shared__ float sm[];
    float* const sA = sm;               // 2 * 8192 floats
    float* const sB = sm + 16384;       // 2 * 16384 floats
    const int tid  = threadIdx.x;
    const int wid  = tid >> 5;
    const int lane = tid & 31;
    const int g = lane >> 2, t = lane & 3;
    const int sw = g << 2;
    const int cta = blockIdx.x;
    const uint32_t sA_u = smem_u32(sA), sB_u = smem_u32(sB);

    auto stage = [&](int q2) {
        const int bf = q2 & 1;
        const float* asrc = g_a2 + ((size_t)cta * 128) * 256 + q2 * 64;
        #pragma unroll
        for (int i = 0; i < 8; ++i) {
            int idx = tid + i * 256;                 // 0..2047
            int j = idx >> 4, c4 = (idx & 15) * 4;
            uint32_t dst = sA_u + (uint32_t)(bf * 8192 + j * 64 + (c4 ^ ((j & 7) << 2))) * 4u;
            CP16(dst, asrc + j * 256 + c4);
        }
        const float* bsrc = g_w2t + q2 * 64;
        #pragma unroll
        for (int i = 0; i < 16; ++i) {
            int idx = tid + i * 256;                 // 0..4095
            int j = idx >> 4, c4 = (idx & 15) * 4;
            uint32_t dst = sB_u + (uint32_t)(bf * 16384 + j * 64 + (c4 ^ ((j & 7) << 2))) * 4u;
            CP16(dst, bsrc + j * 256 + c4);
        }
        CP_COMMIT();
    };
    stage(0);
    stage(1);

    float acc[32][4];
    #pragma unroll
    for (int n = 0; n < 32; ++n)
        #pragma unroll
        for (int e = 0; e < 4; ++e) acc[n][e] = 0.0f;

    const int w16 = wid * 16;
    #pragma unroll 1
    for (int q = 0; q < 4; ++q) {
        if (q == 3) { CP_WAIT(0); } else { CP_WAIT(1); }
        __syncthreads();
        const float* const aw = sA + (q & 1) * 8192 + (w16 + g) * 64;
        const float* const bw = sB + (q & 1) * 16384 + g * 64;
        #pragma unroll
        for (int ks = 0; ks < 8; ++ks) {
            const int o1 = (ks * 8 + t) ^ sw;
            const int o2 = (ks * 8 + t + 4) ^ sw;
            uint32_t a[4];
            a[0] = __float_as_uint(aw[o1]);
            a[1] = __float_as_uint(aw[o1 + 512]);
            a[2] = __float_as_uint(aw[o2]);
            a[3] = __float_as_uint(aw[o2 + 512]);
            #pragma unroll
            for (int n = 0; n < 32; ++n) {
                const uint32_t b0 = __float_as_uint(bw[n * 512 + o1]);
                const uint32_t b1 = __float_as_uint(bw[n * 512 + o2]);
                mma8(acc[n], a, b0, b1);
            }
        }
        __syncthreads();
        if (q + 2 < 4) stage(q + 2);
    }

    const size_t r0 = (size_t)cta * 128 + w16 + g;
    #pragma unroll
    for (int n = 0; n < 32; ++n) {
        *(float2*)(out + r0 * 256 + n * 8 + 2 * t)       = make_float2(acc[n][0], acc[n][1]);
        *(float2*)(out + (r0 + 8) * 256 + n * 8 + 2 * t) = make_float2(acc[n][2], acc[n][3]);
    }
}

extern "C" void kernel_launch(void* const* d_in, const int* in_sizes, int n_in,
                              void* d_out, int out_size) {
    const float* x    = (const float*)d_in[0];
    const float* lnw  = (const float*)d_in[1];
    const float* lnb  = (const float*)d_in[2];
    const float* wqkv = (const float*)d_in[3];
    const float* wout = (const float*)d_in[4];
    const float* relt = (const float*)d_in[5];
    // d_in[6] (rel_pos_indices) is recomputed analytically in-kernel.

    prep_w1<<<768, 256>>>(wqkv);
    prep_w2<<<256, 256>>>(wout);

    cudaFuncSetAttribute(attn_k1, cudaFuncAttributeMaxDynamicSharedMemorySize, K1_SMEM);
    cudaFuncSetAttribute(attn_k2, cudaFuncAttributeMaxDynamicSharedMemorySize, K2_SMEM);
    attn_k1<<<NCTA, 256, K1_SMEM>>>(x, lnw, lnb, relt);
    attn_k2<<<NCTA, 256, K2_SMEM>>>((float*)d_out);
}